// round 10
// baseline (speedup 1.0000x reference)
#include <cuda_runtime.h>
#include <cuda_fp16.h>
#include <cstdint>

#define S_LEN 4096
#define D_MODEL 256
#define NTHREADS 256
#define QPW 4
#define QPB 32            // 8 warps * 4 queries

__device__ __forceinline__ float ex2f(float a) {
    float r; asm("ex2.approx.f32 %0,%1;" : "=f"(r) : "f"(a)); return r;
}
__device__ __forceinline__ __half2 u2h(uint32_t u) {
    return *reinterpret_cast<__half2*>(&u);
}
__device__ __forceinline__ __half2 negabs2(__half2 d) {   // -|d| per half: set sign bits (alu LOP3)
    uint32_t u = *reinterpret_cast<uint32_t*>(&d) | 0x80008000u;
    return *reinterpret_cast<__half2*>(&u);
}

__global__ __launch_bounds__(NTHREADS) void dwsa_kernel(
    const float2* __restrict__ x,   // [B, S, 2] (size, height)
    const float* __restrict__ Wq,
    const float* __restrict__ Wk,
    const float* __restrict__ Wv,
    float* __restrict__ out)        // [B, S, 256]
{
    __shared__ __half2  nszh[S_LEN / 2];   // -lam2*size f16x2 (8 KB)
    __shared__ __half2  hph [S_LEN / 2];   // height f16x2     (8 KB)
    __shared__ float    red[48];

    const int tid  = threadIdx.x;
    const int lane = tid & 31;
    const int warp = tid >> 5;
    const int blocks_per_batch = S_LEN / QPB;    // 128
    const int b  = blockIdx.x / blocks_per_batch;
    const int q0 = (blockIdx.x % blocks_per_batch) * QPB;

    const float LOG2E = 1.4426950408889634f;
    const float LAM2  = 0.5f * LOG2E;

    // --- Stage batch into packed half2 smem; reductions in f32 ---
    const float2* xb  = x + (size_t)b * S_LEN;
    const float4* xb4 = (const float4*)xb;
    float hmax = -1e30f, hmin = 1e30f, szmax = -1e30f, szmin = 1e30f;
    int zflag = 0;
    for (int i = tid; i < S_LEN / 2; i += NTHREADS) {
        float4 v = xb4[i];                        // {sz0, h0, sz1, h1}
        nszh[i] = __floats2half2_rn(-LAM2 * v.x, -LAM2 * v.z);
        hph [i] = __floats2half2_rn(v.y, v.w);
        hmax = fmaxf(hmax, fmaxf(v.y, v.w));   hmin = fminf(hmin, fminf(v.y, v.w));
        szmax = fmaxf(szmax, fmaxf(v.x, v.z)); szmin = fminf(szmin, fminf(v.x, v.z));
        zflag |= (v.y == 0.f) | (v.w == 0.f);
    }
    float cp = Wq[tid] * Wk[tid];                 // NTHREADS == D_MODEL
    #pragma unroll
    for (int o = 16; o > 0; o >>= 1) {
        hmax  = fmaxf(hmax,  __shfl_xor_sync(0xffffffffu, hmax,  o));
        hmin  = fminf(hmin,  __shfl_xor_sync(0xffffffffu, hmin,  o));
        szmax = fmaxf(szmax, __shfl_xor_sync(0xffffffffu, szmax, o));
        szmin = fminf(szmin, __shfl_xor_sync(0xffffffffu, szmin, o));
        cp   += __shfl_xor_sync(0xffffffffu, cp, o);
    }
    if (lane == 0) {
        red[warp] = hmax; red[8+warp] = hmin; red[16+warp] = szmax;
        red[24+warp] = szmin; red[32+warp] = cp;
    }
    const int anyzero = __syncthreads_or(zflag);
    hmax = red[0]; hmin = red[8]; szmax = red[16]; szmin = red[24];
    float csum = red[32];
    #pragma unroll
    for (int w = 1; w < 8; w++) {
        hmax = fmaxf(hmax, red[w]);       hmin = fminf(hmin, red[8+w]);
        szmax = fmaxf(szmax, red[16+w]);  szmin = fminf(szmin, red[24+w]);
        csum += red[32+w];
    }
    const float c = csum * (1.0f / 16.0f);
    const float wspan = LAM2 * (szmax - szmin);

    // --- Four queries per warp: s = q0 + warp + {0,8,16,24} ---
    float qszf[QPW], a2f[QPW], nM2f[QPW];
    #pragma unroll
    for (int q = 0; q < QPW; q++) {
        float2 xq = xb[q0 + warp + q * 8];
        qszf[q] = LAM2 * xq.x;
        a2f[q]  = c * xq.y * LOG2E;
        nM2f[q] = -fmaxf(a2f[q] * hmax, a2f[q] * hmin);
    }

    float zf[QPW], rf[QPW];
    const bool fast = (!anyzero) && (wspan <= 13.0f);

    if (fast) {
        __half2 q2[QPW], a2[QPW], m2[QPW];
        #pragma unroll
        for (int q = 0; q < QPW; q++) {
            q2[q] = __float2half2_rn(qszf[q]);
            a2[q] = __float2half2_rn(a2f[q]);
            m2[q] = __float2half2_rn(nM2f[q]);
        }
        const uint4* nh4 = (const uint4*)nszh;   // 512 uint4: 16 chunks x 32 lanes
        const uint4* hp4 = (const uint4*)hph;

        #pragma unroll
        for (int q = 0; q < QPW; q++) { zf[q] = 0.f; rf[q] = 0.f; }

        for (int g = 0; g < 8; g++) {            // 8 groups x 2 chunks; flush per group
            __half2 z2[QPW], r2[QPW];
            #pragma unroll
            for (int q = 0; q < QPW; q++) {
                z2[q] = __float2half2_rn(0.f);
                r2[q] = __float2half2_rn(0.f);
            }
            #pragma unroll
            for (int ci = 0; ci < 2; ci++) {
                const int j = lane + (g * 2 + ci) * 32;
                uint4 sv = nh4[j];               // 4 half2 = 8 keys (-lam2*sz)
                uint4 hv = hp4[j];               // 4 half2 = 8 heights
                #pragma unroll
                for (int e = 0; e < 4; e++) {
                    uint32_t su = (e == 0) ? sv.x : (e == 1) ? sv.y : (e == 2) ? sv.z : sv.w;
                    uint32_t hu = (e == 0) ? hv.x : (e == 1) ? hv.y : (e == 2) ? hv.z : hv.w;
                    __half2 s2 = u2h(su);
                    __half2 h2 = u2h(hu);
                    #pragma unroll
                    for (int q = 0; q < QPW; q++) {
                        __half2 d2 = __hadd2(q2[q], s2);         // HADD2
                        __half2 n2 = negabs2(d2);                // LOP3 (alu)
                        __half2 t2 = __hfma2(a2[q], h2, m2[q]);  // HFMA2
                        __half2 p2 = h2exp2(__hadd2(t2, n2));    // HADD2 + MUFU
                        z2[q] = __hadd2(z2[q], p2);              // HADD2
                        r2[q] = __hfma2(p2, h2, r2[q]);          // HFMA2
                    }
                }
            }
            #pragma unroll
            for (int q = 0; q < QPW; q++) {
                float2 f;
                f = __half22float2(z2[q]); zf[q] += f.x + f.y;
                f = __half22float2(r2[q]); rf[q] += f.x + f.y;
            }
        }
    } else {
        // ===== Exact f32 fallback (key-masked), reads global x (L1/L2-hot) =====
        #pragma unroll
        for (int q = 0; q < QPW; q++) { zf[q] = 0.f; rf[q] = 0.f; }
        for (int t = lane; t < S_LEN; t += 32) {
            float2 kx = xb[t];
            float ht = kx.y;
            float nszt = -LAM2 * kx.x;
            #pragma unroll
            for (int q = 0; q < QPW; q++) {
                float d = qszf[q] + nszt;
                float p = ex2f(fmaf(a2f[q], ht, nM2f[q]) - fabsf(d));
                if (ht == 0.f) p = 0.f;
                zf[q] += p; rf[q] = fmaf(p, ht, rf[q]);
            }
        }
    }

    const float4* wv4 = (const float4*)Wv;
    #pragma unroll
    for (int q = 0; q < QPW; q++) {
        float z = zf[q], r = rf[q];
        #pragma unroll
        for (int o = 16; o > 0; o >>= 1) {
            z += __shfl_xor_sync(0xffffffffu, z, o);
            r += __shfl_xor_sync(0xffffffffu, r, o);
        }
        const float val = (z > 0.f) ? __fdividef(r, z) : 0.f;
        const int s = q0 + warp + q * 8;
        float4* o4 = (float4*)(out + ((size_t)b * S_LEN + s) * D_MODEL);
        #pragma unroll
        for (int k = 0; k < 2; k++) {
            float4 w = wv4[lane * 2 + k];
            o4[lane * 2 + k] = make_float4(val * w.x, val * w.y, val * w.z, val * w.w);
        }
    }
}

extern "C" void kernel_launch(void* const* d_in, const int* in_sizes, int n_in,
                              void* d_out, int out_size) {
    const float2* x  = (const float2*)d_in[0];
    const float*  Wq = (const float*)d_in[1];
    const float*  Wk = (const float*)d_in[2];
    const float*  Wv = (const float*)d_in[3];
    float* out = (float*)d_out;

    const int B = in_sizes[0] / (S_LEN * 2);
    const int grid = B * (S_LEN / QPB);
    dwsa_kernel<<<grid, NTHREADS>>>(x, Wq, Wk, Wv, out);
}